// round 1
// baseline (speedup 1.0000x reference)
#include <cuda_runtime.h>

// Problem constants
#define N_B 4
#define C_  32
#define L_  8
#define D_  24
#define H_  24
#define W_  24
#define PLANE (H_*W_)          // 576

// smem x tile: 32 ci x 26 x 26 halo plane, row stride padded to 29 (odd -> no bank pattern)
#define XS_WS 29
#define XS_HN 26
#define XS_CI (XS_HN*XS_WS)    // 754
#define XS_SIZE (32*XS_CI)     // 24128 floats
#define WS_SIZE (32*9*32)      // 9216 floats: [ci][tap][co]
#define SMEM_BYTES ((XS_SIZE + WS_SIZE)*4)   // 133376 B

// Reordered weights: [kl][kd][ci][tap(kh*3+kw)][co]
__device__ float g_wre[3*3*32*9*32];   // 82944 floats

__global__ void prep_w_kernel(const float* __restrict__ w) {
    int o = blockIdx.x * 256 + threadIdx.x;
    if (o >= 82944) return;
    int co = o & 31;
    int t  = (o >> 5) % 9;
    int ci = (o / 288) & 31;
    int kd = (o / 9216) % 3;
    int kl = o / 27648;
    // src layout: (ci, co, kl, kd, kh, kw), kh*3+kw == t
    g_wre[o] = w[(ci*32 + co)*81 + kl*27 + kd*9 + t];
}

__global__ void __launch_bounds__(576, 1)
convt4d_kernel(const float* __restrict__ x,
               const float* __restrict__ bias,
               float* __restrict__ out)
{
    extern __shared__ float smem[];
    float* xs = smem;
    float* ws = smem + XS_SIZE;

    const int od = blockIdx.x, ol = blockIdx.y, n = blockIdx.z;
    const int tid = threadIdx.x;
    const int co_base = (tid / 144) * 8;   // 4 groups of 8 output channels
    const int s = tid % 144;               // 24 rows x 6 strips
    const int oh = s / 6;
    const int wbase = (s % 6) * 4;         // 4-wide output strip

    float acc[32];
#pragma unroll
    for (int i = 0; i < 32; i++) acc[i] = 0.f;

    const int l0 = ol > 0 ? ol - 1 : 0;
    const int l1 = ol < L_-1 ? ol + 1 : L_-1;
    const int d0 = od > 0 ? od - 1 : 0;
    const int d1 = od < D_-1 ? od + 1 : D_-1;

    for (int lp = l0; lp <= l1; lp++) {
        const int kl = ol + 1 - lp;
        for (int dp = d0; dp <= d1; dp++) {
            const int kd = od + 1 - dp;
            __syncthreads();   // protect smem from previous iteration's readers

            // ---- stage x plane (n, :, lp, dp, :, :) with halo into smem ----
            const size_t base0 = ((size_t)((n*32)*8 + lp)*24 + dp) * (size_t)PLANE;
            for (int idx = tid; idx < 32*26*26; idx += 576) {
                int ci = idx / 676;
                int r  = idx - ci*676;
                int hh = r / 26;
                int ww = r - hh*26;
                int hp = hh - 1, wp = ww - 1;
                float v = 0.f;
                if ((unsigned)hp < 24u && (unsigned)wp < 24u)
                    v = x[base0 + (size_t)ci*110592 + hp*24 + wp];
                xs[ci*XS_CI + hh*XS_WS + ww] = v;
            }
            // ---- stage weight slab for (kl, kd): [ci][tap][co], contiguous ----
            const float* wsrc = g_wre + (kl*3 + kd)*9216;
            for (int i = tid; i < 9216; i += 576) ws[i] = wsrc[i];
            __syncthreads();

            // ---- compute ----
#pragma unroll 1
            for (int ci = 0; ci < 32; ci++) {
                const float* xci = xs + ci*XS_CI;
                const float* wci = ws + ci*288 + co_base;
#pragma unroll
                for (int kh = 0; kh < 3; kh++) {
                    const float* xrow0 = xci + (oh + 2 - kh)*XS_WS + wbase;
                    float xr[6];
#pragma unroll
                    for (int j = 0; j < 6; j++) xr[j] = xrow0[j];
#pragma unroll
                    for (int kw = 0; kw < 3; kw++) {
                        const float4 wa = *(const float4*)(wci + (kh*3 + kw)*32);
                        const float4 wb = *(const float4*)(wci + (kh*3 + kw)*32 + 4);
                        const float wv[8] = {wa.x, wa.y, wa.z, wa.w,
                                             wb.x, wb.y, wb.z, wb.w};
#pragma unroll
                        for (int co = 0; co < 8; co++) {
#pragma unroll
                            for (int p = 0; p < 4; p++)
                                acc[co*4 + p] += wv[co] * xr[p + 2 - kw];
                        }
                    }
                }
            }
        }
    }

    // ---- bias + vectorized store ----
#pragma unroll
    for (int co = 0; co < 8; co++) {
        int c = co_base + co;
        float b = __ldg(bias + c);
        float4 v;
        v.x = acc[co*4 + 0] + b;
        v.y = acc[co*4 + 1] + b;
        v.z = acc[co*4 + 2] + b;
        v.w = acc[co*4 + 3] + b;
        *(float4*)(out + ((size_t)((n*32 + c)*8 + ol)*24 + od)*PLANE
                       + oh*24 + wbase) = v;
    }
}

extern "C" void kernel_launch(void* const* d_in, const int* in_sizes, int n_in,
                              void* d_out, int out_size) {
    const float* x    = (const float*)d_in[0];
    const float* w    = (const float*)d_in[1];
    const float* bias = (const float*)d_in[2];
    float* out = (float*)d_out;

    cudaFuncSetAttribute(convt4d_kernel,
                         cudaFuncAttributeMaxDynamicSharedMemorySize, SMEM_BYTES);

    prep_w_kernel<<<324, 256>>>(w);          // 324*256 == 82944 exactly

    dim3 grid(D_, L_, N_B);                  // (od, ol, n)
    convt4d_kernel<<<grid, 576, SMEM_BYTES>>>(x, bias, out);
}

// round 2
// speedup vs baseline: 1.1631x; 1.1631x over previous
#include <cuda_runtime.h>
#include <cstdint>

// Problem constants
#define N_B 4
#define C_  32
#define L_  8
#define D_  24
#define H_  24
#define W_  24
#define PLANE (H_*W_)          // 576

// smem x tile: 32 ci x 26 x 26 halo plane, row stride padded to 29
#define XS_WS 29
#define XS_HN 26
#define XS_CI (XS_HN*XS_WS)    // 754
#define XS_SIZE (32*XS_CI)     // 24128 floats
#define WS_SIZE (32*9*32)      // 9216 floats: [ci][tap][co]
#define SMEM_BYTES ((XS_SIZE + WS_SIZE)*4)   // 133376 B

// Reordered weights: [kl][kd][ci][tap(kh*3+kw)][co]
__device__ float g_wre[3*3*32*9*32];   // 82944 floats

__global__ void prep_w_kernel(const float* __restrict__ w) {
    int o = blockIdx.x * 256 + threadIdx.x;
    if (o >= 82944) return;
    int co = o & 31;
    int t  = (o >> 5) % 9;
    int ci = (o / 288) & 31;
    int kd = (o / 9216) % 3;
    int kl = o / 27648;
    // src layout: (ci, co, kl, kd, kh, kw), kh*3+kw == t
    g_wre[o] = w[(ci*32 + co)*81 + kl*27 + kd*9 + t];
}

// ---- Blackwell packed fp32x2 helpers ----
__device__ __forceinline__ void ffma2(uint64_t& d, uint64_t a, uint64_t b) {
    asm("fma.rn.f32x2 %0, %1, %2, %0;" : "+l"(d) : "l"(a), "l"(b));
}
__device__ __forceinline__ uint64_t pack_dup(float v) {
    uint64_t r;
    asm("mov.b64 %0, {%1, %1};" : "=l"(r) : "f"(v));
    return r;
}
__device__ __forceinline__ float2 unpack2(uint64_t v) {
    float2 r;
    asm("mov.b64 {%0, %1}, %2;" : "=f"(r.x), "=f"(r.y) : "l"(v));
    return r;
}

__global__ void __launch_bounds__(576, 1)
convt4d_kernel(const float* __restrict__ x,
               const float* __restrict__ bias,
               float* __restrict__ out)
{
    extern __shared__ float smem[];
    float* xs = smem;
    float* ws = smem + XS_SIZE;

    const int od = blockIdx.x, ol = blockIdx.y, n = blockIdx.z;
    const int tid = threadIdx.x;
    const int co_base = (tid / 144) * 8;   // 4 groups of 8 output channels
    const int s = tid % 144;               // 24 rows x 6 strips
    const int oh = s / 6;
    const int wbase = (s % 6) * 4;         // 4-wide output strip

    // acc[c*4+p]: co-pair c (channels co_base+2c, +2c+1) at spatial offset p
    uint64_t acc[16];
#pragma unroll
    for (int i = 0; i < 16; i++) acc[i] = 0ull;

    const int l0 = ol > 0 ? ol - 1 : 0;
    const int l1 = ol < L_-1 ? ol + 1 : L_-1;
    const int d0 = od > 0 ? od - 1 : 0;
    const int d1 = od < D_-1 ? od + 1 : D_-1;

    for (int lp = l0; lp <= l1; lp++) {
        const int kl = ol + 1 - lp;
        for (int dp = d0; dp <= d1; dp++) {
            const int kd = od + 1 - dp;
            __syncthreads();   // protect smem from previous iteration's readers

            // ---- stage x plane (n, :, lp, dp, :, :) with halo into smem ----
            const size_t base0 = ((size_t)((n*32)*8 + lp)*24 + dp) * (size_t)PLANE;
            for (int idx = tid; idx < 32*26*26; idx += 576) {
                int ci = idx / 676;
                int r  = idx - ci*676;
                int hh = r / 26;
                int ww = r - hh*26;
                int hp = hh - 1, wp = ww - 1;
                float v = 0.f;
                if ((unsigned)hp < 24u && (unsigned)wp < 24u)
                    v = x[base0 + (size_t)ci*110592 + hp*24 + wp];
                xs[ci*XS_CI + hh*XS_WS + ww] = v;
            }
            // ---- stage weight slab for (kl, kd): [ci][tap][co], contiguous ----
            const float* wsrc = g_wre + (kl*3 + kd)*9216;
            for (int i = tid; i < 9216; i += 576) ws[i] = wsrc[i];
            __syncthreads();

            // ---- compute: packed f32x2 over co-pairs ----
#pragma unroll 1
            for (int ci = 0; ci < 32; ci++) {
                const float* xci = xs + ci*XS_CI;
                const float* wci = ws + ci*288 + co_base;
#pragma unroll
                for (int kh = 0; kh < 3; kh++) {
                    const float* xrow0 = xci + (oh + 2 - kh)*XS_WS + wbase;
                    uint64_t xd[6];
#pragma unroll
                    for (int j = 0; j < 6; j++) xd[j] = pack_dup(xrow0[j]);
#pragma unroll
                    for (int kw = 0; kw < 3; kw++) {
                        // two LDS.128 -> four packed co-pair weights
                        const ulonglong2* wp2 =
                            (const ulonglong2*)(wci + (kh*3 + kw)*32);
                        ulonglong2 wA = wp2[0];
                        ulonglong2 wB = wp2[1];
                        uint64_t wv[4] = {wA.x, wA.y, wB.x, wB.y};
#pragma unroll
                        for (int c = 0; c < 4; c++) {
#pragma unroll
                            for (int p = 0; p < 4; p++)
                                ffma2(acc[c*4 + p], wv[c], xd[p + 2 - kw]);
                        }
                    }
                }
            }
        }
    }

    // ---- bias + unpack + vectorized store ----
#pragma unroll
    for (int c = 0; c < 4; c++) {
        const int co0 = co_base + 2*c;
        const float b0 = __ldg(bias + co0);
        const float b1 = __ldg(bias + co0 + 1);
        float4 v0, v1;
        float2 t;
        t = unpack2(acc[c*4 + 0]); v0.x = t.x + b0; v1.x = t.y + b1;
        t = unpack2(acc[c*4 + 1]); v0.y = t.x + b0; v1.y = t.y + b1;
        t = unpack2(acc[c*4 + 2]); v0.z = t.x + b0; v1.z = t.y + b1;
        t = unpack2(acc[c*4 + 3]); v0.w = t.x + b0; v1.w = t.y + b1;
        const size_t o0 = ((size_t)((n*32 + co0)*8 + ol)*24 + od)*PLANE
                          + oh*24 + wbase;
        *(float4*)(out + o0)          = v0;
        *(float4*)(out + o0 + (size_t)8*24*PLANE) = v1;   // next channel
    }
}

extern "C" void kernel_launch(void* const* d_in, const int* in_sizes, int n_in,
                              void* d_out, int out_size) {
    const float* x    = (const float*)d_in[0];
    const float* w    = (const float*)d_in[1];
    const float* bias = (const float*)d_in[2];
    float* out = (float*)d_out;

    cudaFuncSetAttribute(convt4d_kernel,
                         cudaFuncAttributeMaxDynamicSharedMemorySize, SMEM_BYTES);

    prep_w_kernel<<<324, 256>>>(w);          // 324*256 == 82944 exactly

    dim3 grid(D_, L_, N_B);                  // (od, ol, n)
    convt4d_kernel<<<grid, 576, SMEM_BYTES>>>(x, bias, out);
}